// round 9
// baseline (speedup 1.0000x reference)
#include <cuda_runtime.h>

// Inputs (metadata order):
// 0: dist_mat   float32  [4096*4096]
// 1: vector_mat float32  [4096*4096*3]
// 2: forces_out float32  [4096*3]
// 3: params     float32  [N_ANGLES*2]  (k0, theta0)
// 4: coord_idx  int32    [N_ANGLES*3]  (a1, a2, a3)
// 5: calc_energy int32   [1]
// 6: calc_forces int32   [1]
// Output: out[0] = energy, out[1 .. 1+3*N_ATOMS) = forces

#define TPB 256      // threads per block, 1 angle per thread

__global__ void init_out_kernel(float* __restrict__ out,
                                const float* __restrict__ forces_in,
                                int n_forces) {
    int i = blockIdx.x * blockDim.x + threadIdx.x;
    // Let the dependent angle_kernel start its gather prologue immediately;
    // it still waits for our full completion at cudaGridDependencySynchronize().
    if (threadIdx.x == 0) cudaTriggerProgrammaticLaunchCompletion();
    if (i == 0) out[0] = 0.0f;
    if (i < n_forces) out[1 + i] = forces_in[i];
}

// Create an evict_last L2 policy register (fraction 1.0).
__device__ __forceinline__ unsigned long long make_evict_last_policy() {
    unsigned long long pol;
    asm("createpolicy.fractional.L2::evict_last.b64 %0, 1.0;" : "=l"(pol));
    return pol;
}

// dist: 64MB, fits in L2 entirely -> pin with evict_last via cache_hint.
__device__ __forceinline__ float ldg_dist(const float* p, unsigned long long pol) {
    float v;
    asm volatile("ld.global.nc.L2::cache_hint.f32 %0, [%1], %2;"
                 : "=f"(v) : "l"(p), "l"(pol));
    return v;
}

// vec: 192MB, default policy (competes for remaining L2).
__device__ __forceinline__ float2 ldg_v2(const float* p) {
    float2 v;
    asm volatile("ld.global.nc.v2.f32 {%0, %1}, [%2];"
                 : "=f"(v.x), "=f"(v.y) : "l"(p));
    return v;
}

// Branchless 12B gather of vec row r via two 8B-aligned float2 loads.
__device__ __forceinline__ void load_vec3(const float* __restrict__ vec,
                                          size_t r, float& x, float& y, float& z) {
    const int odd = (int)(r & 1);
    const float2 lo = ldg_v2(vec + 3 * r - odd);
    const float2 hi = ldg_v2(vec + 3 * r + 2 - odd);
    x = odd ? lo.y : lo.x;
    y = odd ? hi.x : lo.y;
    z = odd ? hi.y : hi.x;
}

// Branchless force scatter: one red.v2.f32 on the 8B-aligned pair + one scalar.
// base = out + 1 + 3*a ; byte addr of base rel. d_out = 4 + 12a:
//   a odd  -> base 8B-aligned      -> v2 on (x,y), scalar z
//   a even -> base+1 is 8B-aligned -> v2 on (y,z), scalar x
__device__ __forceinline__ void red_force3(float* base, int a,
                                           float fx, float fy, float fz) {
    const int odd = a & 1;
    float* pv = base + (odd ? 0 : 1);
    const float v0 = odd ? fx : fy;
    const float v1 = odd ? fy : fz;
    float* ps = base + (odd ? 2 : 0);
    const float sv = odd ? fz : fx;
    asm volatile("red.global.add.v2.f32 [%0], {%1, %2};"
                 :: "l"(pv), "f"(v0), "f"(v1) : "memory");
    atomicAdd(ps, sv);
}

__global__ void __launch_bounds__(TPB) angle_kernel(
    const float* __restrict__ dist,
    const float* __restrict__ vec,
    const float* __restrict__ params,
    const int*   __restrict__ cidx,
    const int*   __restrict__ calc_e_p,
    const int*   __restrict__ calc_f_p,
    float*       __restrict__ out,
    int n_angles, int n_atoms)
{
    const int j  = blockIdx.x * blockDim.x + threadIdx.x;
    const int ce = __ldg(calc_e_p);
    const int cf = __ldg(calc_f_p);
    float e = 0.0f;

    float f0x = 0.f, f0y = 0.f, f0z = 0.f;
    float f2x = 0.f, f2y = 0.f, f2z = 0.f;
    int a1 = 0, a2 = 0, a3 = 0;
    bool active = (j < n_angles);

    if (active) {
        const unsigned long long pol = make_evict_last_policy();

        // Indices: 12B at cidx+3j, same parity trick as vec3 (two 8B loads).
        const int jodd = j & 1;
        const int2 clo = *(const int2*)(cidx + 3 * j - jodd);
        const int2 chi = *(const int2*)(cidx + 3 * j + 2 - jodd);
        a1 = jodd ? clo.y : clo.x;
        a2 = jodd ? chi.x : clo.y;
        a3 = jodd ? chi.y : chi.x;

        // Params: 8B aligned always.
        const float2 p = *(const float2*)(params + 2 * j);
        const float k0 = p.x, t0 = p.y;

        const size_t r21 = (size_t)a2 * (size_t)n_atoms + (size_t)a1;
        const size_t r23 = (size_t)a2 * (size_t)n_atoms + (size_t)a3;

        // Front-batched gathers: 4x LDG.64 (vec) + 2x LDG.32 (dist, L2-pinned).
        // All of this long-latency work overlaps the init kernel via PDL.
        float v21x, v21y, v21z, v23x, v23y, v23z;
        load_vec3(vec, r21, v21x, v21y, v21z);
        load_vec3(vec, r23, v23x, v23y, v23z);
        const float d21 = ldg_dist(dist + r21, pol);
        const float d23 = ldg_dist(dist + r23, pol);

        float ct = v21x * v23x + v21y * v23y + v21z * v23z;
        ct = fminf(1.0f, fmaxf(-1.0f, ct));

        const float theta = acosf(ct);
        const float dth   = theta - t0;

        e = k0 * dth * dth;

        if (cf) {
            const float st   = sqrtf(fmaxf(0.0f, 1.0f - ct * ct));
            const float coef = (st > 0.0f)
                             ? (-2.0f * k0 * dth / fmaxf(st, 1e-12f))
                             : 0.0f;
            const float c21 = coef / d21;
            const float c23 = coef / d23;

            f0x = c21 * (ct * v21x - v23x);
            f0y = c21 * (ct * v21y - v23y);
            f0z = c21 * (ct * v21z - v23z);
            f2x = c23 * (ct * v23x - v21x);
            f2y = c23 * (ct * v23y - v21y);
            f2z = c23 * (ct * v23z - v21z);
        }
    }

    // Wait for init_out_kernel to fully complete before first write to out.
    cudaGridDependencySynchronize();

    if (active && cf) {
        float* forces = out + 1;
        red_force3(forces + 3 * a1, a1, f0x, f0y, f0z);
        red_force3(forces + 3 * a2, a2,
                   -(f0x + f2x), -(f0y + f2y), -(f0z + f2z));
        red_force3(forces + 3 * a3, a3, f2x, f2y, f2z);
    }

    // Hierarchical energy reduction: warp shuffle -> shared -> one atomic/block.
    if (ce) {
        #pragma unroll
        for (int off = 16; off > 0; off >>= 1)
            e += __shfl_down_sync(0xffffffffu, e, off);

        __shared__ float warp_sums[TPB / 32];
        const int lane = threadIdx.x & 31;
        const int wid  = threadIdx.x >> 5;
        if (lane == 0) warp_sums[wid] = e;
        __syncthreads();

        if (wid == 0) {
            e = (lane < TPB / 32) ? warp_sums[lane] : 0.0f;
            #pragma unroll
            for (int off = (TPB / 64); off > 0; off >>= 1)
                e += __shfl_down_sync(0xffffffffu, e, off);
            if (lane == 0) atomicAdd(out, e);
        }
    }
}

extern "C" void kernel_launch(void* const* d_in, const int* in_sizes, int n_in,
                              void* d_out, int out_size) {
    const float* dist   = (const float*)d_in[0];
    const float* vec    = (const float*)d_in[1];
    const float* f_in   = (const float*)d_in[2];
    const float* params = (const float*)d_in[3];
    const int*   cidx   = (const int*)  d_in[4];
    const int*   ce     = (const int*)  d_in[5];
    const int*   cf     = (const int*)  d_in[6];
    float*       out    = (float*)d_out;

    const int n_angles = in_sizes[4] / 3;
    const int n_forces = in_sizes[2];
    const int n_atoms  = n_forces / 3;

    // Primary: init output buffer.
    {
        const int threads = 256;
        const int blocks  = (n_forces + threads) / threads;
        init_out_kernel<<<blocks, threads>>>(out, f_in, n_forces);
    }

    // Dependent: angle kernel with programmatic stream serialization (PDL) so
    // its gather prologue overlaps init; it grid-syncs before touching out.
    {
        const int blocks = (n_angles + TPB - 1) / TPB;

        cudaLaunchAttribute attrs[1];
        attrs[0].id = cudaLaunchAttributeProgrammaticStreamSerialization;
        attrs[0].val.programmaticStreamSerializationAllowed = 1;

        cudaLaunchConfig_t cfg = {};
        cfg.gridDim  = dim3((unsigned)blocks, 1, 1);
        cfg.blockDim = dim3(TPB, 1, 1);
        cfg.dynamicSmemBytes = 0;
        cfg.stream   = 0;
        cfg.attrs    = attrs;
        cfg.numAttrs = 1;

        cudaLaunchKernelEx(&cfg, angle_kernel, dist, vec, params, cidx, ce, cf,
                           out, n_angles, n_atoms);
    }
}

// round 10
// speedup vs baseline: 1.0094x; 1.0094x over previous
#include <cuda_runtime.h>

// Inputs (metadata order):
// 0: dist_mat   float32  [4096*4096]
// 1: vector_mat float32  [4096*4096*3]
// 2: forces_out float32  [4096*3]
// 3: params     float32  [N_ANGLES*2]  (k0, theta0)
// 4: coord_idx  int32    [N_ANGLES*3]  (a1, a2, a3)
// 5: calc_energy int32   [1]
// 6: calc_forces int32   [1]
// Output: out[0] = energy, out[1 .. 1+3*N_ATOMS) = forces

#define TPB 128      // threads per block, 1 angle per thread

__global__ void init_out_kernel(float* __restrict__ out,
                                const float* __restrict__ forces_in,
                                int n_forces) {
    int i = blockIdx.x * blockDim.x + threadIdx.x;
    if (i == 0) out[0] = 0.0f;
    if (i < n_forces) out[1 + i] = forces_in[i];
}

// L2 policy registers.
__device__ __forceinline__ unsigned long long make_evict_last_policy() {
    unsigned long long pol;
    asm("createpolicy.fractional.L2::evict_last.b64 %0, 1.0;" : "=l"(pol));
    return pol;
}
__device__ __forceinline__ unsigned long long make_evict_first_policy() {
    unsigned long long pol;
    asm("createpolicy.fractional.L2::evict_first.b64 %0, 1.0;" : "=l"(pol));
    return pol;
}

// dist: 64MB, fits in L2 -> pin with evict_last (persists across graph replays).
__device__ __forceinline__ float ldg_dist(const float* p, unsigned long long pol) {
    float v;
    asm volatile("ld.global.nc.L2::cache_hint.f32 %0, [%1], %2;"
                 : "=f"(v) : "l"(p), "l"(pol));
    return v;
}

// vec: 192MB, ~zero reuse -> evict_first so it never displaces dist/idx/params.
__device__ __forceinline__ float2 ldg_v2_ef(const float* p, unsigned long long pol) {
    float2 v;
    asm volatile("ld.global.nc.L2::cache_hint.v2.f32 {%0, %1}, [%2], %3;"
                 : "=f"(v.x), "=f"(v.y) : "l"(p), "l"(pol));
    return v;
}

// Branchless 12B gather of vec row r via two 8B-aligned float2 loads.
__device__ __forceinline__ void load_vec3(const float* __restrict__ vec, size_t r,
                                          unsigned long long pol,
                                          float& x, float& y, float& z) {
    const int odd = (int)(r & 1);
    const float2 lo = ldg_v2_ef(vec + 3 * r - odd, pol);
    const float2 hi = ldg_v2_ef(vec + 3 * r + 2 - odd, pol);
    x = odd ? lo.y : lo.x;
    y = odd ? hi.x : lo.y;
    z = odd ? hi.y : hi.x;
}

// Branchless force scatter: one red.v2.f32 on the 8B-aligned pair + one scalar.
//   a odd  -> base 8B-aligned      -> v2 on (x,y), scalar z
//   a even -> base+1 is 8B-aligned -> v2 on (y,z), scalar x
__device__ __forceinline__ void red_force3(float* base, int a,
                                           float fx, float fy, float fz) {
    const int odd = a & 1;
    float* pv = base + (odd ? 0 : 1);
    const float v0 = odd ? fx : fy;
    const float v1 = odd ? fy : fz;
    float* ps = base + (odd ? 2 : 0);
    const float sv = odd ? fz : fx;
    asm volatile("red.global.add.v2.f32 [%0], {%1, %2};"
                 :: "l"(pv), "f"(v0), "f"(v1) : "memory");
    atomicAdd(ps, sv);
}

__global__ void __launch_bounds__(TPB) angle_kernel(
    const float* __restrict__ dist,
    const float* __restrict__ vec,
    const float* __restrict__ params,
    const int*   __restrict__ cidx,
    const int*   __restrict__ calc_e_p,
    const int*   __restrict__ calc_f_p,
    float*       __restrict__ out,
    int n_angles, int n_atoms)
{
    const int j  = blockIdx.x * blockDim.x + threadIdx.x;
    const int ce = __ldg(calc_e_p);
    const int cf = __ldg(calc_f_p);
    float e = 0.0f;

    if (j < n_angles) {
        const unsigned long long pol_last  = make_evict_last_policy();
        const unsigned long long pol_first = make_evict_first_policy();

        // Indices: 12B at cidx+3j, parity trick (two 8B loads, coalesced).
        const int jodd = j & 1;
        const int2 clo = *(const int2*)(cidx + 3 * j - jodd);
        const int2 chi = *(const int2*)(cidx + 3 * j + 2 - jodd);
        const int a1 = jodd ? clo.y : clo.x;
        const int a2 = jodd ? chi.x : clo.y;
        const int a3 = jodd ? chi.y : chi.x;

        // Params: 8B aligned always.
        const float2 p = *(const float2*)(params + 2 * j);
        const float k0 = p.x, t0 = p.y;

        const size_t r21 = (size_t)a2 * (size_t)n_atoms + (size_t)a1;
        const size_t r23 = (size_t)a2 * (size_t)n_atoms + (size_t)a3;

        // Front-batched gathers; dist (L2-resident) first so its short-latency
        // results retire early, vec (DRAM-latency, evict_first) behind it.
        const float d21 = ldg_dist(dist + r21, pol_last);
        const float d23 = ldg_dist(dist + r23, pol_last);
        float v21x, v21y, v21z, v23x, v23y, v23z;
        load_vec3(vec, r21, pol_first, v21x, v21y, v21z);
        load_vec3(vec, r23, pol_first, v23x, v23y, v23z);

        float ct = v21x * v23x + v21y * v23y + v21z * v23z;
        ct = fminf(1.0f, fmaxf(-1.0f, ct));

        const float theta = acosf(ct);
        const float dth   = theta - t0;

        e = k0 * dth * dth;

        if (cf) {
            const float st   = sqrtf(fmaxf(0.0f, 1.0f - ct * ct));
            const float coef = (st > 0.0f)
                             ? (-2.0f * k0 * dth / fmaxf(st, 1e-12f))
                             : 0.0f;
            const float c21 = coef / d21;
            const float c23 = coef / d23;

            const float f0x = c21 * (ct * v21x - v23x);
            const float f0y = c21 * (ct * v21y - v23y);
            const float f0z = c21 * (ct * v21z - v23z);
            const float f2x = c23 * (ct * v23x - v21x);
            const float f2y = c23 * (ct * v23y - v21y);
            const float f2z = c23 * (ct * v23z - v21z);

            float* forces = out + 1;
            red_force3(forces + 3 * a1, a1, f0x, f0y, f0z);
            red_force3(forces + 3 * a2, a2,
                       -(f0x + f2x), -(f0y + f2y), -(f0z + f2z));
            red_force3(forces + 3 * a3, a3, f2x, f2y, f2z);
        }
    }

    // Hierarchical energy reduction: warp shuffle -> shared -> one atomic/block.
    if (ce) {
        #pragma unroll
        for (int off = 16; off > 0; off >>= 1)
            e += __shfl_down_sync(0xffffffffu, e, off);

        __shared__ float warp_sums[TPB / 32];
        const int lane = threadIdx.x & 31;
        const int wid  = threadIdx.x >> 5;
        if (lane == 0) warp_sums[wid] = e;
        __syncthreads();

        if (wid == 0) {
            e = (lane < TPB / 32) ? warp_sums[lane] : 0.0f;
            #pragma unroll
            for (int off = (TPB / 64); off > 0; off >>= 1)
                e += __shfl_down_sync(0xffffffffu, e, off);
            if (lane == 0) atomicAdd(out, e);
        }
    }
}

extern "C" void kernel_launch(void* const* d_in, const int* in_sizes, int n_in,
                              void* d_out, int out_size) {
    const float* dist   = (const float*)d_in[0];
    const float* vec    = (const float*)d_in[1];
    const float* f_in   = (const float*)d_in[2];
    const float* params = (const float*)d_in[3];
    const int*   cidx   = (const int*)  d_in[4];
    const int*   ce     = (const int*)  d_in[5];
    const int*   cf     = (const int*)  d_in[6];
    float*       out    = (float*)d_out;

    const int n_angles = in_sizes[4] / 3;
    const int n_forces = in_sizes[2];
    const int n_atoms  = n_forces / 3;

    {
        const int threads = 256;
        const int blocks  = (n_forces + threads) / threads;
        init_out_kernel<<<blocks, threads>>>(out, f_in, n_forces);
    }
    {
        const int blocks = (n_angles + TPB - 1) / TPB;
        angle_kernel<<<blocks, TPB>>>(dist, vec, params, cidx, ce, cf,
                                      out, n_angles, n_atoms);
    }
}

// round 11
// speedup vs baseline: 1.1758x; 1.1648x over previous
#include <cuda_runtime.h>

// Inputs (metadata order):
// 0: dist_mat   float32  [4096*4096]
// 1: vector_mat float32  [4096*4096*3]
// 2: forces_out float32  [4096*3]
// 3: params     float32  [N_ANGLES*2]  (k0, theta0)
// 4: coord_idx  int32    [N_ANGLES*3]  (a1, a2, a3)
// 5: calc_energy int32   [1]
// 6: calc_forces int32   [1]
// Output: out[0] = energy, out[1 .. 1+3*N_ATOMS) = forces

#define TPB 256      // threads per block, 1 angle per thread

__global__ void init_out_kernel(float* __restrict__ out,
                                const float* __restrict__ forces_in,
                                int n_forces) {
    int i = blockIdx.x * blockDim.x + threadIdx.x;
    if (i == 0) out[0] = 0.0f;
    if (i < n_forces) out[1 + i] = forces_in[i];
}

// L2 policy registers.
__device__ __forceinline__ unsigned long long make_evict_last_policy() {
    unsigned long long pol;
    asm("createpolicy.fractional.L2::evict_last.b64 %0, 1.0;" : "=l"(pol));
    return pol;
}
__device__ __forceinline__ unsigned long long make_evict_first_policy() {
    unsigned long long pol;
    asm("createpolicy.fractional.L2::evict_first.b64 %0, 1.0;" : "=l"(pol));
    return pol;
}

// dist: 64MB, fits in L2 -> pin with evict_last (persists across graph replays).
__device__ __forceinline__ float ldg_dist(const float* p, unsigned long long pol) {
    float v;
    asm volatile("ld.global.nc.L2::cache_hint.f32 %0, [%1], %2;"
                 : "=f"(v) : "l"(p), "l"(pol));
    return v;
}

// vec: 192MB, ~zero reuse -> evict_first so it never displaces dist/idx/params.
__device__ __forceinline__ float2 ldg_v2_ef(const float* p, unsigned long long pol) {
    float2 v;
    asm volatile("ld.global.nc.L2::cache_hint.v2.f32 {%0, %1}, [%2], %3;"
                 : "=f"(v.x), "=f"(v.y) : "l"(p), "l"(pol));
    return v;
}

// Branchless 12B gather of vec row r via two 8B-aligned float2 loads.
__device__ __forceinline__ void load_vec3(const float* __restrict__ vec, size_t r,
                                          unsigned long long pol,
                                          float& x, float& y, float& z) {
    const int odd = (int)(r & 1);
    const float2 lo = ldg_v2_ef(vec + 3 * r - odd, pol);
    const float2 hi = ldg_v2_ef(vec + 3 * r + 2 - odd, pol);
    x = odd ? lo.y : lo.x;
    y = odd ? hi.x : lo.y;
    z = odd ? hi.y : hi.x;
}

// Branchless force scatter via ONE 16B-aligned red.v4 + predicated scalar.
// s = 1 + 3a (float index of fx in out). For m = a & 3 the 16B-aligned window
// and payload (zero lanes are harmless +0.0f adds to neighbors / energy slot):
//   m=0: v4 {0,fx,fy,fz} @ s-1
//   m=1: v4 {fx,fy,fz,0} @ s
//   m=2: v4 {fy,fz,0,0}  @ s+1   + scalar fx @ s
//   m=3: v4 {0,0,fx,fy}  @ s-2   + scalar fz @ s+2
__device__ __forceinline__ void red_force3(float* __restrict__ out, int a,
                                           float fx, float fy, float fz) {
    const int s = 1 + 3 * a;
    const int m = a & 3;

    int voff;            // v4 window offset from out
    float w0, w1, w2, w3;
    switch (m) {         // compiles to SEL chains (uniform-free, per-lane)
        case 0:  voff = s - 1; w0 = 0.f; w1 = fx;  w2 = fy;  w3 = fz;  break;
        case 1:  voff = s;     w0 = fx;  w1 = fy;  w2 = fz;  w3 = 0.f; break;
        case 2:  voff = s + 1; w0 = fy;  w1 = fz;  w2 = 0.f; w3 = 0.f; break;
        default: voff = s - 2; w0 = 0.f; w1 = 0.f; w2 = fx;  w3 = fy;  break;
    }
    asm volatile("red.global.add.v4.f32 [%0], {%1, %2, %3, %4};"
                 :: "l"(out + voff), "f"(w0), "f"(w1), "f"(w2), "f"(w3)
                 : "memory");

    if (m >= 2) {        // predicated scalar for the component the v4 missed
        float* ps = out + (m == 2 ? s : s + 2);
        const float sv = (m == 2) ? fx : fz;
        atomicAdd(ps, sv);
    }
}

__global__ void __launch_bounds__(TPB) angle_kernel(
    const float* __restrict__ dist,
    const float* __restrict__ vec,
    const float* __restrict__ params,
    const int*   __restrict__ cidx,
    const int*   __restrict__ calc_e_p,
    const int*   __restrict__ calc_f_p,
    float*       __restrict__ out,
    int n_angles, int n_atoms)
{
    const int j  = blockIdx.x * blockDim.x + threadIdx.x;
    const int ce = __ldg(calc_e_p);
    const int cf = __ldg(calc_f_p);
    float e = 0.0f;

    if (j < n_angles) {
        const unsigned long long pol_last  = make_evict_last_policy();
        const unsigned long long pol_first = make_evict_first_policy();

        // Indices: 12B at cidx+3j, parity trick (two 8B loads, coalesced).
        const int jodd = j & 1;
        const int2 clo = *(const int2*)(cidx + 3 * j - jodd);
        const int2 chi = *(const int2*)(cidx + 3 * j + 2 - jodd);
        const int a1 = jodd ? clo.y : clo.x;
        const int a2 = jodd ? chi.x : clo.y;
        const int a3 = jodd ? chi.y : chi.x;

        // Params: 8B aligned always.
        const float2 p = *(const float2*)(params + 2 * j);
        const float k0 = p.x, t0 = p.y;

        const size_t r21 = (size_t)a2 * (size_t)n_atoms + (size_t)a1;
        const size_t r23 = (size_t)a2 * (size_t)n_atoms + (size_t)a3;

        // Front-batched gathers; dist (L2-resident) first, vec behind it.
        const float d21 = ldg_dist(dist + r21, pol_last);
        const float d23 = ldg_dist(dist + r23, pol_last);
        float v21x, v21y, v21z, v23x, v23y, v23z;
        load_vec3(vec, r21, pol_first, v21x, v21y, v21z);
        load_vec3(vec, r23, pol_first, v23x, v23y, v23z);

        float ct = v21x * v23x + v21y * v23y + v21z * v23z;
        ct = fminf(1.0f, fmaxf(-1.0f, ct));

        const float theta = acosf(ct);
        const float dth   = theta - t0;

        e = k0 * dth * dth;

        if (cf) {
            const float st   = sqrtf(fmaxf(0.0f, 1.0f - ct * ct));
            const float coef = (st > 0.0f)
                             ? (-2.0f * k0 * dth / fmaxf(st, 1e-12f))
                             : 0.0f;
            const float c21 = coef / d21;
            const float c23 = coef / d23;

            const float f0x = c21 * (ct * v21x - v23x);
            const float f0y = c21 * (ct * v21y - v23y);
            const float f0z = c21 * (ct * v21z - v23z);
            const float f2x = c23 * (ct * v23x - v21x);
            const float f2y = c23 * (ct * v23y - v21y);
            const float f2z = c23 * (ct * v23z - v21z);

            red_force3(out, a1, f0x, f0y, f0z);
            red_force3(out, a2, -(f0x + f2x), -(f0y + f2y), -(f0z + f2z));
            red_force3(out, a3, f2x, f2y, f2z);
        }
    }

    // Hierarchical energy reduction: warp shuffle -> shared -> one atomic/block.
    if (ce) {
        #pragma unroll
        for (int off = 16; off > 0; off >>= 1)
            e += __shfl_down_sync(0xffffffffu, e, off);

        __shared__ float warp_sums[TPB / 32];
        const int lane = threadIdx.x & 31;
        const int wid  = threadIdx.x >> 5;
        if (lane == 0) warp_sums[wid] = e;
        __syncthreads();

        if (wid == 0) {
            e = (lane < TPB / 32) ? warp_sums[lane] : 0.0f;
            #pragma unroll
            for (int off = (TPB / 64); off > 0; off >>= 1)
                e += __shfl_down_sync(0xffffffffu, e, off);
            if (lane == 0) atomicAdd(out, e);
        }
    }
}

extern "C" void kernel_launch(void* const* d_in, const int* in_sizes, int n_in,
                              void* d_out, int out_size) {
    const float* dist   = (const float*)d_in[0];
    const float* vec    = (const float*)d_in[1];
    const float* f_in   = (const float*)d_in[2];
    const float* params = (const float*)d_in[3];
    const int*   cidx   = (const int*)  d_in[4];
    const int*   ce     = (const int*)  d_in[5];
    const int*   cf     = (const int*)  d_in[6];
    float*       out    = (float*)d_out;

    const int n_angles = in_sizes[4] / 3;
    const int n_forces = in_sizes[2];
    const int n_atoms  = n_forces / 3;

    {
        const int threads = 256;
        const int blocks  = (n_forces + threads) / threads;
        init_out_kernel<<<blocks, threads>>>(out, f_in, n_forces);
    }
    {
        const int blocks = (n_angles + TPB - 1) / TPB;
        angle_kernel<<<blocks, TPB>>>(dist, vec, params, cidx, ce, cf,
                                      out, n_angles, n_atoms);
    }
}

// round 12
// speedup vs baseline: 1.4290x; 1.2154x over previous
#include <cuda_runtime.h>

// Inputs (metadata order):
// 0: dist_mat   float32  [4096*4096]
// 1: vector_mat float32  [4096*4096*3]
// 2: forces_out float32  [4096*3]
// 3: params     float32  [N_ANGLES*2]  (k0, theta0)
// 4: coord_idx  int32    [N_ANGLES*3]  (a1, a2, a3)
// 5: calc_energy int32   [1]
// 6: calc_forces int32   [1]
// Output: out[0] = energy, out[1 .. 1+3*N_ATOMS) = forces

#define TPB 256            // threads per block, 1 angle per thread
#define MAX_ATOMS 4096

// Padded per-atom force accumulator: one 16B slot per atom -> every scatter is
// a single aligned red.v4. Zero-initialized at load; each fold re-zeros it, so
// every kernel_launch invocation sees it zeroed on entry (deterministic).
__device__ float4 g_scratch[MAX_ATOMS];

__global__ void zero_energy_kernel(float* __restrict__ out) {
    out[0] = 0.0f;
}

// Fold: out-forces = forces_in + scratch, then re-zero scratch.
__global__ void fold_kernel(float* __restrict__ out,
                            const float* __restrict__ forces_in,
                            int n_atoms) {
    int a = blockIdx.x * blockDim.x + threadIdx.x;
    if (a < n_atoms) {
        const float4 s = g_scratch[a];
        out[1 + 3 * a + 0] = forces_in[3 * a + 0] + s.x;
        out[1 + 3 * a + 1] = forces_in[3 * a + 1] + s.y;
        out[1 + 3 * a + 2] = forces_in[3 * a + 2] + s.z;
        g_scratch[a] = make_float4(0.f, 0.f, 0.f, 0.f);
    }
}

// L2 policy registers.
__device__ __forceinline__ unsigned long long make_evict_last_policy() {
    unsigned long long pol;
    asm("createpolicy.fractional.L2::evict_last.b64 %0, 1.0;" : "=l"(pol));
    return pol;
}
__device__ __forceinline__ unsigned long long make_evict_first_policy() {
    unsigned long long pol;
    asm("createpolicy.fractional.L2::evict_first.b64 %0, 1.0;" : "=l"(pol));
    return pol;
}

// dist: 64MB, fits in L2 -> pin with evict_last (persists across graph replays).
__device__ __forceinline__ float ldg_dist(const float* p, unsigned long long pol) {
    float v;
    asm volatile("ld.global.nc.L2::cache_hint.f32 %0, [%1], %2;"
                 : "=f"(v) : "l"(p), "l"(pol));
    return v;
}

// vec: 192MB, ~zero reuse -> evict_first so it never displaces dist/idx/params.
__device__ __forceinline__ float2 ldg_v2_ef(const float* p, unsigned long long pol) {
    float2 v;
    asm volatile("ld.global.nc.L2::cache_hint.v2.f32 {%0, %1}, [%2], %3;"
                 : "=f"(v.x), "=f"(v.y) : "l"(p), "l"(pol));
    return v;
}

// Branchless 12B gather of vec row r via two 8B-aligned float2 loads.
__device__ __forceinline__ void load_vec3(const float* __restrict__ vec, size_t r,
                                          unsigned long long pol,
                                          float& x, float& y, float& z) {
    const int odd = (int)(r & 1);
    const float2 lo = ldg_v2_ef(vec + 3 * r - odd, pol);
    const float2 hi = ldg_v2_ef(vec + 3 * r + 2 - odd, pol);
    x = odd ? lo.y : lo.x;
    y = odd ? hi.x : lo.y;
    z = odd ? hi.y : hi.x;
}

// One aligned 16B RED per atom into the padded scratch accumulator.
__device__ __forceinline__ void red_force3(int a, float fx, float fy, float fz) {
    asm volatile("red.global.add.v4.f32 [%0], {%1, %2, %3, %4};"
                 :: "l"(&g_scratch[a]), "f"(fx), "f"(fy), "f"(fz), "f"(0.f)
                 : "memory");
}

__global__ void __launch_bounds__(TPB) angle_kernel(
    const float* __restrict__ dist,
    const float* __restrict__ vec,
    const float* __restrict__ params,
    const int*   __restrict__ cidx,
    const int*   __restrict__ calc_e_p,
    const int*   __restrict__ calc_f_p,
    float*       __restrict__ out,
    int n_angles, int n_atoms)
{
    const int j  = blockIdx.x * blockDim.x + threadIdx.x;
    const int ce = __ldg(calc_e_p);
    const int cf = __ldg(calc_f_p);
    float e = 0.0f;

    if (j < n_angles) {
        const unsigned long long pol_last  = make_evict_last_policy();
        const unsigned long long pol_first = make_evict_first_policy();

        // Indices: 12B at cidx+3j, parity trick (two 8B loads, coalesced).
        const int jodd = j & 1;
        const int2 clo = *(const int2*)(cidx + 3 * j - jodd);
        const int2 chi = *(const int2*)(cidx + 3 * j + 2 - jodd);
        const int a1 = jodd ? clo.y : clo.x;
        const int a2 = jodd ? chi.x : clo.y;
        const int a3 = jodd ? chi.y : chi.x;

        // Params: 8B aligned always.
        const float2 p = *(const float2*)(params + 2 * j);
        const float k0 = p.x, t0 = p.y;

        const size_t r21 = (size_t)a2 * (size_t)n_atoms + (size_t)a1;
        const size_t r23 = (size_t)a2 * (size_t)n_atoms + (size_t)a3;

        // Front-batched gathers; dist (L2-resident) first, vec behind it.
        const float d21 = ldg_dist(dist + r21, pol_last);
        const float d23 = ldg_dist(dist + r23, pol_last);
        float v21x, v21y, v21z, v23x, v23y, v23z;
        load_vec3(vec, r21, pol_first, v21x, v21y, v21z);
        load_vec3(vec, r23, pol_first, v23x, v23y, v23z);

        float ct = v21x * v23x + v21y * v23y + v21z * v23z;
        ct = fminf(1.0f, fmaxf(-1.0f, ct));

        const float theta = acosf(ct);
        const float dth   = theta - t0;

        e = k0 * dth * dth;

        if (cf) {
            const float st   = sqrtf(fmaxf(0.0f, 1.0f - ct * ct));
            const float coef = (st > 0.0f)
                             ? (-2.0f * k0 * dth / fmaxf(st, 1e-12f))
                             : 0.0f;
            const float c21 = coef / d21;
            const float c23 = coef / d23;

            const float f0x = c21 * (ct * v21x - v23x);
            const float f0y = c21 * (ct * v21y - v23y);
            const float f0z = c21 * (ct * v21z - v23z);
            const float f2x = c23 * (ct * v23x - v21x);
            const float f2y = c23 * (ct * v23y - v21y);
            const float f2z = c23 * (ct * v23z - v21z);

            red_force3(a1, f0x, f0y, f0z);
            red_force3(a2, -(f0x + f2x), -(f0y + f2y), -(f0z + f2z));
            red_force3(a3, f2x, f2y, f2z);
        }
    }

    // Hierarchical energy reduction: warp shuffle -> shared -> one atomic/block.
    if (ce) {
        #pragma unroll
        for (int off = 16; off > 0; off >>= 1)
            e += __shfl_down_sync(0xffffffffu, e, off);

        __shared__ float warp_sums[TPB / 32];
        const int lane = threadIdx.x & 31;
        const int wid  = threadIdx.x >> 5;
        if (lane == 0) warp_sums[wid] = e;
        __syncthreads();

        if (wid == 0) {
            e = (lane < TPB / 32) ? warp_sums[lane] : 0.0f;
            #pragma unroll
            for (int off = (TPB / 64); off > 0; off >>= 1)
                e += __shfl_down_sync(0xffffffffu, e, off);
            if (lane == 0) atomicAdd(out, e);
        }
    }
}

extern "C" void kernel_launch(void* const* d_in, const int* in_sizes, int n_in,
                              void* d_out, int out_size) {
    const float* dist   = (const float*)d_in[0];
    const float* vec    = (const float*)d_in[1];
    const float* f_in   = (const float*)d_in[2];
    const float* params = (const float*)d_in[3];
    const int*   cidx   = (const int*)  d_in[4];
    const int*   ce     = (const int*)  d_in[5];
    const int*   cf     = (const int*)  d_in[6];
    float*       out    = (float*)d_out;

    const int n_angles = in_sizes[4] / 3;
    const int n_forces = in_sizes[2];
    const int n_atoms  = n_forces / 3;

    // 1) Zero the energy slot (forces are produced wholly by fold_kernel).
    zero_energy_kernel<<<1, 1>>>(out);

    // 2) Main: gathers + 3x aligned red.v4 into scratch + energy reduction.
    {
        const int blocks = (n_angles + TPB - 1) / TPB;
        angle_kernel<<<blocks, TPB>>>(dist, vec, params, cidx, ce, cf,
                                      out, n_angles, n_atoms);
    }

    // 3) Fold scratch + forces_in into out, re-zeroing scratch for next call.
    {
        const int threads = 256;
        const int blocks  = (n_atoms + threads - 1) / threads;
        fold_kernel<<<blocks, threads>>>(out, f_in, n_atoms);
    }
}

// round 13
// speedup vs baseline: 1.4608x; 1.0222x over previous
#include <cuda_runtime.h>

// Inputs (metadata order):
// 0: dist_mat   float32  [4096*4096]
// 1: vector_mat float32  [4096*4096*3]
// 2: forces_out float32  [4096*3]
// 3: params     float32  [N_ANGLES*2]  (k0, theta0)
// 4: coord_idx  int32    [N_ANGLES*3]  (a1, a2, a3)
// 5: calc_energy int32   [1]
// 6: calc_forces int32   [1]
// Output: out[0] = energy, out[1 .. 1+3*N_ATOMS) = forces

#define TPB 256            // threads per block, 1 angle per thread
#define MAX_ATOMS 4096

// Padded per-atom force accumulator: one 16B slot per atom -> every scatter is
// a single aligned red.v4. Zero-initialized at load; fold_kernel re-zeros it,
// so every kernel_launch invocation sees it zeroed on entry (deterministic).
__device__ float4 g_scratch[MAX_ATOMS];
// Energy accumulator, same lifecycle (zero at entry, re-zeroed by fold).
__device__ float  g_energy;

// Fold: out-forces = forces_in + scratch; out-energy = g_energy.
// Re-zeros both accumulators for the next replay.
__global__ void fold_kernel(float* __restrict__ out,
                            const float* __restrict__ forces_in,
                            int n_atoms) {
    int a = blockIdx.x * blockDim.x + threadIdx.x;
    if (a < n_atoms) {
        const float4 s = g_scratch[a];
        out[1 + 3 * a + 0] = forces_in[3 * a + 0] + s.x;
        out[1 + 3 * a + 1] = forces_in[3 * a + 1] + s.y;
        out[1 + 3 * a + 2] = forces_in[3 * a + 2] + s.z;
        g_scratch[a] = make_float4(0.f, 0.f, 0.f, 0.f);
    }
    if (a == 0) {
        out[0]   = g_energy;
        g_energy = 0.0f;
    }
}

// L2 policy registers.
__device__ __forceinline__ unsigned long long make_evict_last_policy() {
    unsigned long long pol;
    asm("createpolicy.fractional.L2::evict_last.b64 %0, 1.0;" : "=l"(pol));
    return pol;
}
__device__ __forceinline__ unsigned long long make_evict_first_policy() {
    unsigned long long pol;
    asm("createpolicy.fractional.L2::evict_first.b64 %0, 1.0;" : "=l"(pol));
    return pol;
}

// dist: 64MB, fits in L2 -> pin with evict_last (persists across graph replays).
__device__ __forceinline__ float ldg_dist(const float* p, unsigned long long pol) {
    float v;
    asm volatile("ld.global.nc.L2::cache_hint.f32 %0, [%1], %2;"
                 : "=f"(v) : "l"(p), "l"(pol));
    return v;
}

// vec: 192MB, ~zero reuse -> evict_first so it never displaces dist/idx/params.
__device__ __forceinline__ float2 ldg_v2_ef(const float* p, unsigned long long pol) {
    float2 v;
    asm volatile("ld.global.nc.L2::cache_hint.v2.f32 {%0, %1}, [%2], %3;"
                 : "=f"(v.x), "=f"(v.y) : "l"(p), "l"(pol));
    return v;
}

// Branchless 12B gather of vec row r via two 8B-aligned float2 loads.
__device__ __forceinline__ void load_vec3(const float* __restrict__ vec, size_t r,
                                          unsigned long long pol,
                                          float& x, float& y, float& z) {
    const int odd = (int)(r & 1);
    const float2 lo = ldg_v2_ef(vec + 3 * r - odd, pol);
    const float2 hi = ldg_v2_ef(vec + 3 * r + 2 - odd, pol);
    x = odd ? lo.y : lo.x;
    y = odd ? hi.x : lo.y;
    z = odd ? hi.y : hi.x;
}

// One aligned 16B RED per atom into the padded scratch accumulator.
__device__ __forceinline__ void red_force3(int a, float fx, float fy, float fz) {
    asm volatile("red.global.add.v4.f32 [%0], {%1, %2, %3, %4};"
                 :: "l"(&g_scratch[a]), "f"(fx), "f"(fy), "f"(fz), "f"(0.f)
                 : "memory");
}

__global__ void __launch_bounds__(TPB) angle_kernel(
    const float* __restrict__ dist,
    const float* __restrict__ vec,
    const float* __restrict__ params,
    const int*   __restrict__ cidx,
    const int*   __restrict__ calc_e_p,
    const int*   __restrict__ calc_f_p,
    int n_angles, int n_atoms)
{
    const int j  = blockIdx.x * blockDim.x + threadIdx.x;
    const int ce = __ldg(calc_e_p);
    const int cf = __ldg(calc_f_p);
    float e = 0.0f;

    if (j < n_angles) {
        const unsigned long long pol_last  = make_evict_last_policy();
        const unsigned long long pol_first = make_evict_first_policy();

        // Indices: 12B at cidx+3j, parity trick (two 8B loads, coalesced).
        const int jodd = j & 1;
        const int2 clo = *(const int2*)(cidx + 3 * j - jodd);
        const int2 chi = *(const int2*)(cidx + 3 * j + 2 - jodd);
        const int a1 = jodd ? clo.y : clo.x;
        const int a2 = jodd ? chi.x : clo.y;
        const int a3 = jodd ? chi.y : chi.x;

        // Params: 8B aligned always.
        const float2 p = *(const float2*)(params + 2 * j);
        const float k0 = p.x, t0 = p.y;

        const size_t r21 = (size_t)a2 * (size_t)n_atoms + (size_t)a1;
        const size_t r23 = (size_t)a2 * (size_t)n_atoms + (size_t)a3;

        // Front-batched gathers; dist (L2-resident) first, vec behind it.
        const float d21 = ldg_dist(dist + r21, pol_last);
        const float d23 = ldg_dist(dist + r23, pol_last);
        float v21x, v21y, v21z, v23x, v23y, v23z;
        load_vec3(vec, r21, pol_first, v21x, v21y, v21z);
        load_vec3(vec, r23, pol_first, v23x, v23y, v23z);

        float ct = v21x * v23x + v21y * v23y + v21z * v23z;
        ct = fminf(1.0f, fmaxf(-1.0f, ct));

        const float theta = acosf(ct);
        const float dth   = theta - t0;

        e = k0 * dth * dth;

        if (cf) {
            const float st   = sqrtf(fmaxf(0.0f, 1.0f - ct * ct));
            const float coef = (st > 0.0f)
                             ? (-2.0f * k0 * dth / fmaxf(st, 1e-12f))
                             : 0.0f;
            const float c21 = coef / d21;
            const float c23 = coef / d23;

            const float f0x = c21 * (ct * v21x - v23x);
            const float f0y = c21 * (ct * v21y - v23y);
            const float f0z = c21 * (ct * v21z - v23z);
            const float f2x = c23 * (ct * v23x - v21x);
            const float f2y = c23 * (ct * v23y - v21y);
            const float f2z = c23 * (ct * v23z - v21z);

            red_force3(a1, f0x, f0y, f0z);
            red_force3(a2, -(f0x + f2x), -(f0y + f2y), -(f0z + f2z));
            red_force3(a3, f2x, f2y, f2z);
        }
    }

    // Hierarchical energy reduction into g_energy (zero at entry; folded+reset
    // by fold_kernel): warp shuffle -> shared -> one atomic/block.
    if (ce) {
        #pragma unroll
        for (int off = 16; off > 0; off >>= 1)
            e += __shfl_down_sync(0xffffffffu, e, off);

        __shared__ float warp_sums[TPB / 32];
        const int lane = threadIdx.x & 31;
        const int wid  = threadIdx.x >> 5;
        if (lane == 0) warp_sums[wid] = e;
        __syncthreads();

        if (wid == 0) {
            e = (lane < TPB / 32) ? warp_sums[lane] : 0.0f;
            #pragma unroll
            for (int off = (TPB / 64); off > 0; off >>= 1)
                e += __shfl_down_sync(0xffffffffu, e, off);
            if (lane == 0) atomicAdd(&g_energy, e);
        }
    }
}

extern "C" void kernel_launch(void* const* d_in, const int* in_sizes, int n_in,
                              void* d_out, int out_size) {
    const float* dist   = (const float*)d_in[0];
    const float* vec    = (const float*)d_in[1];
    const float* f_in   = (const float*)d_in[2];
    const float* params = (const float*)d_in[3];
    const int*   cidx   = (const int*)  d_in[4];
    const int*   ce     = (const int*)  d_in[5];
    const int*   cf     = (const int*)  d_in[6];
    float*       out    = (float*)d_out;

    const int n_angles = in_sizes[4] / 3;
    const int n_forces = in_sizes[2];
    const int n_atoms  = n_forces / 3;

    // 1) Main: gathers + 3x aligned red.v4 into scratch + energy into g_energy.
    {
        const int blocks = (n_angles + TPB - 1) / TPB;
        angle_kernel<<<blocks, TPB>>>(dist, vec, params, cidx, ce, cf,
                                      n_angles, n_atoms);
    }

    // 2) Fold scratch + forces_in into out (and energy), re-zeroing scratch.
    {
        const int threads = 256;
        const int blocks  = (n_atoms + threads - 1) / threads;
        fold_kernel<<<blocks, threads>>>(out, f_in, n_atoms);
    }
}